// round 11
// baseline (speedup 1.0000x reference)
#include <cuda_runtime.h>

// Fused hyper-connection:
//   out[b,t,m,c] = sum_n x[b,t,n,c] * ( res_w[m,n] + softmax(post)[m]*softmax(pre)[n] )
// Flat oversubscribed launch at the measured HBM roofline (~6.33 TB/s mixed
// R/W). Each thread handles TWO float4 columns (stride 128 float4 so every
// load instruction stays lane-contiguous): 8 front-batched loads (MLP_p1=8),
// 4x4 linear map, 8 streaming stores. W computed per-block into smem.
// Block 1024 -> 2048 CTAs (fewest scheduling events for this pattern).

__global__ __launch_bounds__(1024)
void hc_fused_kernel(const float4* __restrict__ x, float4* __restrict__ out,
                     const float* __restrict__ pre,
                     const float* __restrict__ post,
                     const float* __restrict__ res) {
    __shared__ float sW[16];
    if (threadIdx.x == 0) {
        float pw[4], qw[4];
        float m1 = -1e30f, m2 = -1e30f;
        #pragma unroll
        for (int i = 0; i < 4; i++) {
            m1 = fmaxf(m1, pre[i]);
            m2 = fmaxf(m2, post[i]);
        }
        float s1 = 0.f, s2 = 0.f;
        #pragma unroll
        for (int i = 0; i < 4; i++) {
            pw[i] = __expf(pre[i] - m1);  s1 += pw[i];
            qw[i] = __expf(post[i] - m2); s2 += qw[i];
        }
        const float r1 = 1.f / s1, r2 = 1.f / s2;
        #pragma unroll
        for (int m = 0; m < 4; m++)
            #pragma unroll
            for (int n = 0; n < 4; n++)
                sW[m * 4 + n] = res[m * 4 + n] + (qw[m] * r2) * (pw[n] * r1);
    }
    __syncthreads();

    const unsigned idx = blockIdx.x * 1024u + threadIdx.x;
    const unsigned row = idx >> 7;        // 0 .. 16383  (B*T rows)
    const unsigned c4  = idx & 127u;      // 0 .. 127    (first of 2 float4 cols)

    const size_t base = (size_t)row * 1024 + c4;  // float4 units

    // 8 front-batched loads: n-slice stride 256, column stride 128
    float4 xn[4][2];
    #pragma unroll
    for (int n = 0; n < 4; n++)
        #pragma unroll
        for (int j = 0; j < 2; j++)
            xn[n][j] = __ldcs(&x[base + (size_t)n * 256 + (size_t)j * 128]);

    float W[16];
    #pragma unroll
    for (int i = 0; i < 16; i++)
        W[i] = sW[i];

    #pragma unroll
    for (int m = 0; m < 4; m++) {
        #pragma unroll
        for (int j = 0; j < 2; j++) {
            float4 o;
            o.x = W[m*4+0]*xn[0][j].x + W[m*4+1]*xn[1][j].x + W[m*4+2]*xn[2][j].x + W[m*4+3]*xn[3][j].x;
            o.y = W[m*4+0]*xn[0][j].y + W[m*4+1]*xn[1][j].y + W[m*4+2]*xn[2][j].y + W[m*4+3]*xn[3][j].y;
            o.z = W[m*4+0]*xn[0][j].z + W[m*4+1]*xn[1][j].z + W[m*4+2]*xn[2][j].z + W[m*4+3]*xn[3][j].z;
            o.w = W[m*4+0]*xn[0][j].w + W[m*4+1]*xn[1][j].w + W[m*4+2]*xn[2][j].w + W[m*4+3]*xn[3][j].w;
            __stcs(&out[base + (size_t)m * 256 + (size_t)j * 128], o);
        }
    }
}

extern "C" void kernel_launch(void* const* d_in, const int* in_sizes, int n_in,
                              void* d_out, int out_size) {
    const float* x    = (const float*)d_in[0];
    const float* pre  = (const float*)d_in[1];
    const float* post = (const float*)d_in[2];
    const float* res  = (const float*)d_in[3];
    float* out = (float*)d_out;

    // 16384 rows x 128 threads/row = 2.097M threads, 2048 blocks of 1024
    const unsigned total_threads = 16384u * 128u;
    hc_fused_kernel<<<total_threads / 1024u, 1024u>>>(
        (const float4*)x, (float4*)out, pre, post, res);
}

// round 13
// speedup vs baseline: 1.0051x; 1.0051x over previous
#include <cuda_runtime.h>

// Fused hyper-connection (FINAL, converged at HBM roofline):
//   out[b,t,m,c] = sum_n x[b,t,n,c] * ( res_w[m,n] + softmax(post)[m]*softmax(pre)[n] )
// Single fused kernel: W = res_w + post_sm (x) pre_sm computed per-block into
// smem, then a pure 256MB->256MB stream at the measured mixed-R/W HBM sustain
// ceiling (~6.33 TB/s, 80% of spec). Each thread handles TWO float4 columns
// (stride 128 float4 so every load instruction stays lane-contiguous):
// 8 front-batched loads (MLP_p1=8), 4x4 linear map, 8 streaming stores.
// 512 threads/block -> 4 resident CTAs/SM (>=4 residency required; 1 CTA/SM
// and persistent-loop variants measured 6% slower).

__global__ __launch_bounds__(512)
void hc_fused_kernel(const float4* __restrict__ x, float4* __restrict__ out,
                     const float* __restrict__ pre,
                     const float* __restrict__ post,
                     const float* __restrict__ res) {
    __shared__ float sW[16];
    if (threadIdx.x == 0) {
        float pw[4], qw[4];
        float m1 = -1e30f, m2 = -1e30f;
        #pragma unroll
        for (int i = 0; i < 4; i++) {
            m1 = fmaxf(m1, pre[i]);
            m2 = fmaxf(m2, post[i]);
        }
        float s1 = 0.f, s2 = 0.f;
        #pragma unroll
        for (int i = 0; i < 4; i++) {
            pw[i] = __expf(pre[i] - m1);  s1 += pw[i];
            qw[i] = __expf(post[i] - m2); s2 += qw[i];
        }
        const float r1 = 1.f / s1, r2 = 1.f / s2;
        #pragma unroll
        for (int m = 0; m < 4; m++)
            #pragma unroll
            for (int n = 0; n < 4; n++)
                sW[m * 4 + n] = res[m * 4 + n] + (qw[m] * r2) * (pw[n] * r1);
    }
    __syncthreads();

    const unsigned idx = blockIdx.x * 512u + threadIdx.x;
    const unsigned row = idx >> 7;        // 0 .. 16383  (B*T rows)
    const unsigned c4  = idx & 127u;      // 0 .. 127    (first of 2 float4 cols)

    const size_t base = (size_t)row * 1024 + c4;  // float4 units

    // 8 front-batched loads: n-slice stride 256, column stride 128
    float4 xn[4][2];
    #pragma unroll
    for (int n = 0; n < 4; n++)
        #pragma unroll
        for (int j = 0; j < 2; j++)
            xn[n][j] = __ldcs(&x[base + (size_t)n * 256 + (size_t)j * 128]);

    float W[16];
    #pragma unroll
    for (int i = 0; i < 16; i++)
        W[i] = sW[i];

    #pragma unroll
    for (int m = 0; m < 4; m++) {
        #pragma unroll
        for (int j = 0; j < 2; j++) {
            float4 o;
            o.x = W[m*4+0]*xn[0][j].x + W[m*4+1]*xn[1][j].x + W[m*4+2]*xn[2][j].x + W[m*4+3]*xn[3][j].x;
            o.y = W[m*4+0]*xn[0][j].y + W[m*4+1]*xn[1][j].y + W[m*4+2]*xn[2][j].y + W[m*4+3]*xn[3][j].y;
            o.z = W[m*4+0]*xn[0][j].z + W[m*4+1]*xn[1][j].z + W[m*4+2]*xn[2][j].z + W[m*4+3]*xn[3][j].z;
            o.w = W[m*4+0]*xn[0][j].w + W[m*4+1]*xn[1][j].w + W[m*4+2]*xn[2][j].w + W[m*4+3]*xn[3][j].w;
            __stcs(&out[base + (size_t)m * 256 + (size_t)j * 128], o);
        }
    }
}

extern "C" void kernel_launch(void* const* d_in, const int* in_sizes, int n_in,
                              void* d_out, int out_size) {
    const float* x    = (const float*)d_in[0];
    const float* pre  = (const float*)d_in[1];
    const float* post = (const float*)d_in[2];
    const float* res  = (const float*)d_in[3];
    float* out = (float*)d_out;

    // 16384 rows x 128 threads/row = 2.097M threads, 4096 blocks of 512
    const unsigned total_threads = 16384u * 128u;
    hc_fused_kernel<<<total_threads / 512u, 512u>>>(
        (const float4*)x, (float4*)out, pre, post, res);
}